// round 12
// baseline (speedup 1.0000x reference)
#include <cuda_runtime.h>

// Problem constants (fixed by the reference):
//   x:    (B=32, T=1024, N=512, C=3) float32, innermost stride 1 over C
//   perm: (B, NB=512) int32, per-batch block permutation (PS=2, NB=T/PS)
// out[b,t,n,0] = x[b, perm[b, t/PS]*PS + t%PS, n, 0]
// out[b,t,n,c] = x[b, t, n, c]  for c in {1,2}
static constexpr int Bdim = 32;
static constexpr int Tdim = 1024;
static constexpr int Ndim = 512;
static constexpr int Cdim = 3;
static constexpr int PS   = 2;
static constexpr int NB   = Tdim / PS;              // 512
static constexpr unsigned TOTAL_PTS = (unsigned)Bdim * Tdim * Ndim;  // 16,777,216

__global__ void __launch_bounds__(256)
patch_perm_kernel(const float* __restrict__ x,
                  const int*   __restrict__ perm,
                  float*       __restrict__ out)
{
    unsigned p = blockIdx.x * blockDim.x + threadIdx.x;
    if (p >= TOTAL_PTS) return;

    // Decompose p -> (b, t, n). All divisors are powers of two -> shifts.
    unsigned n  = p & (Ndim - 1);
    unsigned bt = p >> 9;                 // p / 512
    unsigned t  = bt & (Tdim - 1);
    unsigned b  = bt >> 10;               // bt / 1024

    // Gather source row for channel 0 (uniform across the warp: same b,t).
    int tsrc = __ldg(&perm[b * NB + (t >> 1)]) * PS + (int)(t & 1u);

    unsigned dst  = p * 3u;                                    // (b,t,n)*C
    unsigned src0 = (((b * Tdim + (unsigned)tsrc) * Ndim) + n) * 3u;

    out[dst + 0] = __ldg(&x[src0]);
    out[dst + 1] = __ldg(&x[dst + 1]);
    out[dst + 2] = __ldg(&x[dst + 2]);
}

extern "C" void kernel_launch(void* const* d_in, const int* in_sizes, int n_in,
                              void* d_out, int out_size)
{
    const float* x    = (const float*)d_in[0];
    const int*   perm = (const int*)  d_in[1];
    float*       out  = (float*)d_out;

    const int threads = 256;
    const int blocks  = (TOTAL_PTS + threads - 1) / threads;   // 65536
    patch_perm_kernel<<<blocks, threads>>>(x, perm, out);
}